// round 10
// baseline (speedup 1.0000x reference)
#include <cuda_runtime.h>
#include <cstdint>
#include <cstdio>
#include <cmath>

// Problem constants
#define BATCH 64
#define TSEQ  1024
#define FDIM  512
#define IDIM  256
#define SDIM  128
#define MDIM  64
#define BT    (BATCH*TSEQ)           // 65536
#define UNFOLDS 6

// ---------------- device scratch (no device allocs allowed) ----------------
__device__ float  g_hidden[BT*IDIM];
__device__ float  g_gate  [BT*SDIM];
__device__ float  g_C     [BT*SDIM];
__device__ float  g_m     [BT*SDIM];
__device__ float  g_wns   [BT*SDIM];
__device__ float  g_wds   [BT*SDIM];
__device__ float  g_fused [BT*SDIM];
__device__ float  g_final [BATCH*SDIM];
__device__ float2 g_sens_ab[IDIM*SDIM];   // device-internal only
__device__ float2 g_sens_wv[IDIM*SDIM];   // device-internal only
__device__ float2 g_rec_ab [SDIM*SDIM];   // device-internal only
__device__ float  g_rec_wh [SDIM*SDIM];   // device-internal only
__device__ float  g_rec_we [SDIM*SDIM];   // device-internal only
__device__ float  g_cns[SDIM], g_cds[SDIM], g_cnr[SDIM], g_cdr[SDIM];

__device__ __forceinline__ float tanh_fast(float x) {
    float y;
    asm("tanh.approx.f32 %0, %1;" : "=f"(y) : "f"(x));
    return y;
}

// ---------------- generic fp32 GEMM: out = A[M,K] @ B[K,N] + bias ----------------
template<int KDIM, int NDIM, int MODE>
__global__ void __launch_bounds__(256) sgemm_kernel(
    const float* __restrict__ A, const float* __restrict__ B,
    const float* __restrict__ bias,
    float* __restrict__ out0, float* __restrict__ out1)
{
    constexpr int BM = 128, BN = 64, BK = 16;
    __shared__ float As[BK][BM];
    __shared__ float Bs[BK][BN];

    const int tid  = threadIdx.x;
    const int bx   = blockIdx.x;
    const int by   = blockIdx.y;
    const int tRow = tid >> 4;
    const int tCol = tid & 15;

    float acc[8][4];
#pragma unroll
    for (int i = 0; i < 8; i++)
#pragma unroll
        for (int j = 0; j < 4; j++) acc[i][j] = 0.f;

    const int aRow = tid >> 2;
    const int aC   = (tid & 3) * 4;
    const int bRow = tid >> 4;
    const int bC   = (tid & 15) * 4;

    for (int kt = 0; kt < KDIM; kt += BK) {
#pragma unroll
        for (int l = 0; l < 2; l++) {
            int r = aRow + l * 64;
            float4 v = *reinterpret_cast<const float4*>(
                &A[(size_t)(bx * BM + r) * KDIM + kt + aC]);
            As[aC + 0][r] = v.x; As[aC + 1][r] = v.y;
            As[aC + 2][r] = v.z; As[aC + 3][r] = v.w;
        }
        {
            float4 v = *reinterpret_cast<const float4*>(
                &B[(size_t)(kt + bRow) * NDIM + by * BN + bC]);
            *reinterpret_cast<float4*>(&Bs[bRow][bC]) = v;
        }
        __syncthreads();
#pragma unroll
        for (int k = 0; k < BK; k++) {
            float am[8], bn[4];
#pragma unroll
            for (int i = 0; i < 8; i++) am[i] = As[k][tRow * 8 + i];
#pragma unroll
            for (int j = 0; j < 4; j++) bn[j] = Bs[k][tCol * 4 + j];
#pragma unroll
            for (int i = 0; i < 8; i++)
#pragma unroll
                for (int j = 0; j < 4; j++)
                    acc[i][j] = fmaf(am[i], bn[j], acc[i][j]);
        }
        __syncthreads();
    }

#pragma unroll
    for (int i = 0; i < 8; i++) {
#pragma unroll
        for (int j = 0; j < 4; j++) {
            size_t row = (size_t)bx * BM + tRow * 8 + i;
            int col = by * BN + tCol * 4 + j;
            float v = acc[i][j] + bias[col];
            if (MODE == 0) {
                v = tanhf(v);
                if (col < IDIM) out0[row * IDIM + col] = v;
                else            out1[row * SDIM + (col - IDIM)] = v;
            } else if (MODE == 1) {
                out0[row * SDIM + col] = v;
            } else {
                out0[row * MDIM + col] = v;
            }
        }
    }
}

// ---------------- parameter transform + per-s constant sums ----------------
__global__ void param_prep(
    const float* __restrict__ w,   const float* __restrict__ sigma,
    const float* __restrict__ mu,  const float* __restrict__ erev,
    const float* __restrict__ mask,
    const float* __restrict__ sw_, const float* __restrict__ ssig,
    const float* __restrict__ smu, const float* __restrict__ serev,
    const float* __restrict__ smask)
{
    int s = threadIdx.x;  // 128 threads, 1 block
    float cns = 0.f, cds = 0.f;
    for (int i = 0; i < IDIM; i++) {
        int idx = i * SDIM + s;
        float a  = 0.5f * ssig[idx];
        g_sens_ab[idx] = make_float2(a, -smu[idx] * a);
        float wh = 0.5f * sw_[idx] * smask[idx];
        float we = wh * serev[idx];
        g_sens_wv[idx] = make_float2(we, wh);
        cns += we; cds += wh;
    }
    g_cns[s] = cns; g_cds[s] = cds;

    float cnr = 0.f, cdr = 0.f;
    for (int j = 0; j < SDIM; j++) {
        int idx = j * SDIM + s;
        float a  = 0.5f * sigma[idx];
        g_rec_ab[idx] = make_float2(a, -mu[idx] * a);
        float wh = 0.5f * w[idx] * mask[idx];
        float we = wh * erev[idx];
        g_rec_wh[idx] = wh; g_rec_we[idx] = we;
        cnr += we; cdr += wh;
    }
    g_cnr[s] = cnr; g_cdr[s] = cdr;
}

// ---------------- softmax over T (axis=1) + sigmoid + multiply by C ----------------
// reads g_gate, g_C; writes g_m (all device-symbol-internal)
__global__ void __launch_bounds__(512) softmax_m_kernel()
{
    __shared__ float red[512];
    const int b = blockIdx.x, tid = threadIdx.x;
    const int s = tid & 127, tc = tid >> 7;
    const float* g  = g_gate + (size_t)b * TSEQ * SDIM;
    const float* Cb = g_C    + (size_t)b * TSEQ * SDIM;
    float*       mb = g_m    + (size_t)b * TSEQ * SDIM;
    const int t0 = tc * 256;

    float mx = -1e30f;
    for (int t = t0; t < t0 + 256; t++) mx = fmaxf(mx, g[t * SDIM + s]);
    red[tid] = mx;
    __syncthreads();
    mx = fmaxf(fmaxf(red[s], red[128 + s]), fmaxf(red[256 + s], red[384 + s]));
    __syncthreads();

    float sum = 0.f;
    for (int t = t0; t < t0 + 256; t++) sum += __expf(g[t * SDIM + s] - mx);
    red[tid] = sum;
    __syncthreads();
    sum = red[s] + red[128 + s] + red[256 + s] + red[384 + s];
    float inv = __fdividef(1.0f, sum);

    for (int t = t0; t < t0 + 256; t++) {
        float e  = __expf(g[t * SDIM + s] - mx) * inv;
        float sg = fmaf(0.5f, tanh_fast(0.5f * e), 0.5f);  // sigmoid(e)
        mb[t * SDIM + s] = Cb[t * SDIM + s] * sg;
    }
}

// ---------------- sensory precompute ----------------
// hidden passed as RESOLVED device pointer; writes g_wns/g_wds by symbol
__global__ void __launch_bounds__(128) sensory_kernel(const float* __restrict__ hidden)
{
    __shared__ float h_sm[16][IDIM];
    const int tid = threadIdx.x;
    const size_t row0 = (size_t)blockIdx.x * 16;

    for (int idx = tid; idx < 16 * IDIM; idx += 128)
        h_sm[idx >> 8][idx & 255] = hidden[row0 * IDIM + idx];
    __syncthreads();

    const int s = tid;
    float an[16], ad[16];
#pragma unroll
    for (int r = 0; r < 16; r++) { an[r] = 0.f; ad[r] = 0.f; }

    for (int i = 0; i < IDIM; i++) {
        float2 ab = g_sens_ab[i * SDIM + s];
        float2 wv = g_sens_wv[i * SDIM + s];
#pragma unroll
        for (int r = 0; r < 16; r++) {
            float th = tanh_fast(fmaf(h_sm[r][i], ab.x, ab.y));
            an[r] = fmaf(wv.x, th, an[r]);
            ad[r] = fmaf(wv.y, th, ad[r]);
        }
    }
    const float cn = g_cns[s], cd = g_cds[s];
#pragma unroll
    for (int r = 0; r < 16; r++) {
        g_wns[(row0 + r) * SDIM + s] = an[r] + cn;
        g_wds[(row0 + r) * SDIM + s] = ad[r] + cd;
    }
}

// ---------------- sequential ODE scan ----------------
// reads g_wns/g_wds/g_m/g_rec_* by symbol; writes g_fused/g_final by symbol
__global__ void __launch_bounds__(512) scan_kernel(
    const float* __restrict__ ode_state,
    const float* __restrict__ gleak, const float* __restrict__ vleak,
    const float* __restrict__ cm)
{
    __shared__ float v_sm[SDIM];
    __shared__ float red[1024];

    const int b = blockIdx.x, tid = threadIdx.x;
    const int s = tid & 127, jg = tid >> 7;

    float whr[32], wer[32];
#pragma unroll
    for (int k = 0; k < 32; k++) {
        int j = jg * 32 + k;
        whr[k] = g_rec_wh[j * SDIM + s];
        wer[k] = g_rec_we[j * SDIM + s];
    }

    float cmt = 0.f, gl = 0.f, glvl = 0.f, crn = 0.f, crd = 0.f;
    if (jg == 0) {
        cmt  = 6.0f * cm[s];
        gl   = gleak[s];
        glvl = gl * vleak[s];
        crn  = g_cnr[s];
        crd  = g_cdr[s];
        v_sm[s] = ode_state[b * SDIM + s];
    }
    __syncthreads();

    const float* wnsb = g_wns   + (size_t)b * TSEQ * SDIM;
    const float* wdsb = g_wds   + (size_t)b * TSEQ * SDIM;
    const float* mb   = g_m     + (size_t)b * TSEQ * SDIM;
    float*       fb   = g_fused + (size_t)b * TSEQ * SDIM;

    const float2* __restrict__ abg = g_rec_ab;

    for (int t = 0; t < TSEQ; t++) {
        float wn = 0.f, wd = 0.f, mt = 0.f;
        if (jg == 0) {
            wn = wnsb[t * SDIM + s];
            wd = wdsb[t * SDIM + s];
            mt = mb  [t * SDIM + s];
        }
#pragma unroll 1
        for (int u = 0; u < UNFOLDS; u++) {
            float pn = 0.f, pd = 0.f;
#pragma unroll
            for (int k = 0; k < 32; k++) {
                int j = jg * 32 + k;
                float  vj = v_sm[j];
                float2 p  = __ldg(&abg[j * SDIM + s]);
                float  th = tanh_fast(fmaf(vj, p.x, p.y));
                pn = fmaf(wer[k], th, pn);
                pd = fmaf(whr[k], th, pd);
            }
            red[tid]       = pn;
            red[512 + tid] = pd;
            __syncthreads();
            if (jg == 0) {
                float num = fmaf(cmt, v_sm[s], glvl) + wn + crn
                          + red[s] + red[128 + s] + red[256 + s] + red[384 + s];
                float den = cmt + gl + wd + crd
                          + red[512 + s] + red[640 + s] + red[768 + s] + red[896 + s];
                v_sm[s] = __fdividef(num, den + 1e-8f);
            }
            __syncthreads();
        }
        if (jg == 0) fb[t * SDIM + s] = v_sm[s] * mt;
    }
    if (jg == 0) g_final[b * SDIM + s] = v_sm[s];
}

// ---------------- pack tail outputs ----------------
__global__ void __launch_bounds__(256) pack_tail_kernel(float* __restrict__ dst)
{
    long i = (long)blockIdx.x * 256 + threadIdx.x;
    const long nf = (long)BATCH * SDIM;
    const long nu = (long)BT * SDIM;
    if (i < nf) dst[i] = g_final[i];
    else if (i < nf + nu) dst[i] = g_fused[i - nf];
}

// ---------------- trap kernel: poison context so dumps surface on rc!=0 --------
__global__ void hx_trap_kernel() { asm volatile("trap;"); }

// ================= host-side spot reference (b=0, t=0..7) =================
#define HX_TCHK 8
static float h_inp[TSEQ*FDIM];
static float h_Win[FDIM*(IDIM+SDIM)], h_bin[IDIM+SDIM];
static float h_Wc[IDIM*SDIM], h_bc[SDIM];
static float h_Wout[SDIM*MDIM], h_bout[MDIM];
static float h_gl[SDIM], h_vl[SDIM], h_cmv[SDIM], h_ode[SDIM];
static float h_w[SDIM*SDIM], h_sg[SDIM*SDIM], h_muv[SDIM*SDIM], h_er[SDIM*SDIM], h_msk[SDIM*SDIM];
static float h_sw[IDIM*SDIM], h_ssg[IDIM*SDIM], h_smu[IDIM*SDIM], h_ser[IDIM*SDIM], h_smsk[IDIM*SDIM];
static float h_hid[TSEQ*IDIM], h_gt[TSEQ*SDIM];
static float h_mr[HX_TCHK*SDIM];
static float h_wnsr[HX_TCHK*SDIM], h_wdsr[HX_TCHK*SDIM];
static float h_fusedr[HX_TCHK*SDIM], h_outr[HX_TCHK*MDIM];

static inline float hsig(float x) { return 1.0f / (1.0f + expf(-x)); }

// gross-failure counter: only wildly-wrong values count toward trapping
static int hx_cmp_row(const char* name, const float* dev, const float* ref, int n) {
    int gross = 0; int firstbad = -1;
    for (int i = 0; i < n; i++) {
        float d = fabsf(dev[i] - ref[i]);
        if (d > 0.02f + 0.05f * fabsf(ref[i])) { if (firstbad < 0) firstbad = i; gross++; }
    }
    if (gross) {
        fprintf(stderr, "HXDBG STAGE-GROSS %s: %d/%d, first@%d dev=%g ref=%g (d0=%g r0=%g)\n",
                name, gross, n, firstbad, dev[firstbad], ref[firstbad], dev[0], ref[0]);
    }
    return (gross * 4 > n) ? 1 : 0;   // trap only if >25% grossly wrong
}

// ---------------- launch ----------------
extern "C" void kernel_launch(void* const* d_in, const int* in_sizes, int n_in,
                              void* d_out, int out_size)
{
    const float* inputs   = (const float*)d_in[0];
    const float* ode_st   = (const float*)d_in[1];
    const float* W_in     = (const float*)d_in[2];
    const float* b_in     = (const float*)d_in[3];
    const float* W_c      = (const float*)d_in[4];
    const float* b_c      = (const float*)d_in[5];
    const float* W_out    = (const float*)d_in[6];
    const float* b_out    = (const float*)d_in[7];
    const float* gleak    = (const float*)d_in[8];
    const float* vleak    = (const float*)d_in[9];
    const float* cm       = (const float*)d_in[10];
    const float* w        = (const float*)d_in[11];
    const float* sigma    = (const float*)d_in[12];
    const float* mu       = (const float*)d_in[13];
    const float* sens_w   = (const float*)d_in[14];
    const float* sens_sig = (const float*)d_in[15];
    const float* sens_mu  = (const float*)d_in[16];
    const float* erev     = (const float*)d_in[17];
    const float* sens_er  = (const float*)d_in[18];
    const float* mask     = (const float*)d_in[19];
    const float* sens_msk = (const float*)d_in[20];

    float* outputs = (float*)d_out;

    // THE FIX: resolve true device addresses of scratch arrays before passing
    // them as kernel arguments. (Passing the symbol directly from host code
    // passes the host shadow address — on GB300's ATS this silently "works"
    // into host memory instead of faulting.)
    float *p_hidden = nullptr, *p_gate = nullptr, *p_C = nullptr, *p_fused = nullptr;
    cudaGetSymbolAddress((void**)&p_hidden, g_hidden);
    cudaGetSymbolAddress((void**)&p_gate,   g_gate);
    cudaGetSymbolAddress((void**)&p_C,      g_C);
    cudaGetSymbolAddress((void**)&p_fused,  g_fused);

    // ---------------- device pipeline (graph-capturable) ----------------
    param_prep<<<1, 128>>>(w, sigma, mu, erev, mask,
                           sens_w, sens_sig, sens_mu, sens_er, sens_msk);
    sgemm_kernel<FDIM, IDIM + SDIM, 0><<<dim3(BT / 128, (IDIM + SDIM) / 64), 256>>>(
        inputs, W_in, b_in, p_hidden, p_gate);
    sgemm_kernel<IDIM, SDIM, 1><<<dim3(BT / 128, SDIM / 64), 256>>>(
        p_hidden, W_c, b_c, p_C, nullptr);
    softmax_m_kernel<<<BATCH, 512>>>();
    sensory_kernel<<<BT / 16, 128>>>(p_hidden);
    scan_kernel<<<BATCH, 512>>>(ode_st, gleak, vleak, cm);
    sgemm_kernel<SDIM, MDIM, 2><<<dim3(BT / 128, 1), 256>>>(
        p_fused, W_out, b_out, outputs, nullptr);

    long total3 = (long)BT * MDIM + (long)BATCH * SDIM + (long)BT * SDIM;
    if ((long)out_size >= total3) {
        long tail = (long)BATCH * SDIM + (long)BT * SDIM;
        pack_tail_kernel<<<(int)((tail + 255) / 256), 256>>>(outputs + (long)BT * MDIM);
    }

    // ---------------- self-check (non-capture call only) ----------------
    cudaStreamCaptureStatus cs = cudaStreamCaptureStatusNone;
    cudaError_t qe = cudaStreamIsCapturing((cudaStream_t)0, &cs);
    if (qe != cudaSuccess || cs != cudaStreamCaptureStatusNone) return;

    cudaError_t se = cudaDeviceSynchronize();
    if (se != cudaSuccess) {
        fprintf(stderr, "HXDBG pipeline sync error: %s\n", cudaGetErrorString(se));
        fflush(stderr);
        hx_trap_kernel<<<1, 1>>>(); cudaDeviceSynchronize();
        return;
    }

    // host spot reference for b=0, t=0..HX_TCHK-1
    cudaMemcpy(h_inp, inputs, sizeof(h_inp), cudaMemcpyDeviceToHost);
    cudaMemcpy(h_Win, W_in, sizeof(h_Win), cudaMemcpyDeviceToHost);
    cudaMemcpy(h_bin, b_in, sizeof(h_bin), cudaMemcpyDeviceToHost);
    cudaMemcpy(h_Wc,  W_c,  sizeof(h_Wc),  cudaMemcpyDeviceToHost);
    cudaMemcpy(h_bc,  b_c,  sizeof(h_bc),  cudaMemcpyDeviceToHost);
    cudaMemcpy(h_Wout,W_out,sizeof(h_Wout),cudaMemcpyDeviceToHost);
    cudaMemcpy(h_bout,b_out,sizeof(h_bout),cudaMemcpyDeviceToHost);
    cudaMemcpy(h_gl, gleak, sizeof(h_gl), cudaMemcpyDeviceToHost);
    cudaMemcpy(h_vl, vleak, sizeof(h_vl), cudaMemcpyDeviceToHost);
    cudaMemcpy(h_cmv, cm,  sizeof(h_cmv), cudaMemcpyDeviceToHost);
    cudaMemcpy(h_ode,ode_st,sizeof(h_ode),cudaMemcpyDeviceToHost);
    cudaMemcpy(h_w,  w,    sizeof(h_w),  cudaMemcpyDeviceToHost);
    cudaMemcpy(h_sg, sigma,sizeof(h_sg), cudaMemcpyDeviceToHost);
    cudaMemcpy(h_muv,mu,   sizeof(h_muv),cudaMemcpyDeviceToHost);
    cudaMemcpy(h_er, erev, sizeof(h_er), cudaMemcpyDeviceToHost);
    cudaMemcpy(h_msk,mask, sizeof(h_msk),cudaMemcpyDeviceToHost);
    cudaMemcpy(h_sw, sens_w,  sizeof(h_sw), cudaMemcpyDeviceToHost);
    cudaMemcpy(h_ssg,sens_sig,sizeof(h_ssg),cudaMemcpyDeviceToHost);
    cudaMemcpy(h_smu,sens_mu, sizeof(h_smu),cudaMemcpyDeviceToHost);
    cudaMemcpy(h_ser,sens_er, sizeof(h_ser),cudaMemcpyDeviceToHost);
    cudaMemcpy(h_smsk,sens_msk,sizeof(h_smsk),cudaMemcpyDeviceToHost);

    for (int t = 0; t < TSEQ; t++) {
        for (int c = 0; c < IDIM + SDIM; c++) {
            float acc = h_bin[c];
            const float* xr = &h_inp[t * FDIM];
            const float* wc = &h_Win[c];
            for (int f = 0; f < FDIM; f++) acc += xr[f] * wc[(size_t)f * (IDIM + SDIM)];
            float v = tanhf(acc);
            if (c < IDIM) h_hid[t * IDIM + c] = v;
            else          h_gt[t * SDIM + (c - IDIM)] = v;
        }
    }
    for (int s = 0; s < SDIM; s++) {
        float mx = -1e30f;
        for (int t = 0; t < TSEQ; t++) mx = fmaxf(mx, h_gt[t * SDIM + s]);
        float sum = 0.f;
        for (int t = 0; t < TSEQ; t++) sum += expf(h_gt[t * SDIM + s] - mx);
        for (int t = 0; t < HX_TCHK; t++) {
            float e = expf(h_gt[t * SDIM + s] - mx) / sum;
            float Cts = h_bc[s];
            for (int i = 0; i < IDIM; i++) Cts += h_hid[t * IDIM + i] * h_Wc[i * SDIM + s];
            h_mr[t * SDIM + s] = Cts * hsig(e);
        }
    }
    for (int t = 0; t < HX_TCHK; t++)
        for (int s = 0; s < SDIM; s++) {
            float an = 0.f, ad = 0.f;
            for (int i = 0; i < IDIM; i++) {
                int idx = i * SDIM + s;
                float act = h_sw[idx] * hsig((h_hid[t * IDIM + i] - h_smu[idx]) * h_ssg[idx]) * h_smsk[idx];
                an += act * h_ser[idx];
                ad += act;
            }
            h_wnsr[t * SDIM + s] = an;
            h_wdsr[t * SDIM + s] = ad;
        }
    {
        float v[SDIM];
        for (int s = 0; s < SDIM; s++) v[s] = h_ode[s];
        for (int t = 0; t < HX_TCHK; t++) {
            for (int u = 0; u < UNFOLDS; u++) {
                float nv[SDIM];
                for (int s = 0; s < SDIM; s++) {
                    float wn = h_wnsr[t * SDIM + s], wd = h_wdsr[t * SDIM + s];
                    for (int j = 0; j < SDIM; j++) {
                        int idx = j * SDIM + s;
                        float act = h_w[idx] * hsig((v[j] - h_muv[idx]) * h_sg[idx]) * h_msk[idx];
                        wn += act * h_er[idx];
                        wd += act;
                    }
                    float cmt = 6.0f * h_cmv[s];
                    float num = cmt * v[s] + h_gl[s] * h_vl[s] + wn;
                    float den = cmt + h_gl[s] + wd;
                    nv[s] = num / (den + 1e-8f);
                }
                for (int s = 0; s < SDIM; s++) v[s] = nv[s];
            }
            for (int s = 0; s < SDIM; s++)
                h_fusedr[t * SDIM + s] = v[s] * h_mr[t * SDIM + s];
            for (int mo = 0; mo < MDIM; mo++) {
                float acc = h_bout[mo];
                for (int s = 0; s < SDIM; s++)
                    acc += h_fusedr[t * SDIM + s] * h_Wout[s * MDIM + mo];
                h_outr[t * MDIM + mo] = acc;
            }
        }
    }

    int fail = 0;
    static float dv[HX_TCHK * SDIM];
    cudaMemcpy(dv, p_hidden, 256 * sizeof(float), cudaMemcpyDeviceToHost);
    fail += hx_cmp_row("hidden[t0]", dv, h_hid, 256);
    cudaMemcpyFromSymbol(dv, g_m, HX_TCHK * SDIM * sizeof(float));
    fail += hx_cmp_row("m[t0..7]", dv, h_mr, HX_TCHK * SDIM);
    cudaMemcpyFromSymbol(dv, g_wns, HX_TCHK * SDIM * sizeof(float));
    fail += hx_cmp_row("wns[t0..7]", dv, h_wnsr, HX_TCHK * SDIM);
    cudaMemcpy(dv, p_fused, HX_TCHK * SDIM * sizeof(float), cudaMemcpyDeviceToHost);
    fail += hx_cmp_row("fused[t0..7]", dv, h_fusedr, HX_TCHK * SDIM);
    static float dout[HX_TCHK * MDIM];
    cudaMemcpy(dout, d_out, sizeof(dout), cudaMemcpyDeviceToHost);
    fail += hx_cmp_row("out[t0..7]", dout, h_outr, HX_TCHK * MDIM);

    if (fail) {
        fprintf(stderr, "HXDBG GROSS-FAIL stages=%d out_size=%d\n", fail, out_size);
        fflush(stderr);
        hx_trap_kernel<<<1, 1>>>();
        cudaDeviceSynchronize();
    } else {
        fprintf(stderr, "HXDBG SELF-CHECK OK out0=%g ref0=%g\n", dout[0], h_outr[0]);
    }
}

// round 13
// speedup vs baseline: 1.8068x; 1.8068x over previous
#include <cuda_runtime.h>
#include <cuda_fp16.h>
#include <cstdint>

// Problem constants
#define BATCH 64
#define TSEQ  1024
#define FDIM  512
#define IDIM  256
#define SDIM  128
#define MDIM  64
#define BT    (BATCH*TSEQ)           // 65536
#define UNFOLDS 6
#define NPAIR (SDIM/2)               // 64 j-pairs

// ---------------- device scratch (no device allocs allowed) ----------------
__device__ float  g_hidden[BT*IDIM];
__device__ float  g_gate  [BT*SDIM];
__device__ float  g_C     [BT*SDIM];
__device__ float  g_m     [BT*SDIM];
__device__ float  g_wns   [BT*SDIM];
__device__ float  g_wds   [BT*SDIM];
__device__ float2 g_sens_ab[IDIM*SDIM];   // (0.5*sig, -0.5*mu*sig)
__device__ float2 g_sens_wv[IDIM*SDIM];   // (0.5*w*m*erev, 0.5*w*m)
__device__ uint2  g_rec_ab2[NPAIR*SDIM];  // packed half2 (a_j0,a_j1),(b_j0,b_j1)
__device__ float  g_rec_wh [SDIM*SDIM];
__device__ float  g_rec_we [SDIM*SDIM];
__device__ float  g_cns[SDIM], g_cds[SDIM], g_cnr[SDIM], g_cdr[SDIM];

__device__ __forceinline__ float tanh_fast(float x) {
    float y;
    asm("tanh.approx.f32 %0, %1;" : "=f"(y) : "f"(x));
    return y;
}
__device__ __forceinline__ uint32_t tanh_h2(uint32_t x) {
    uint32_t y;
    asm("tanh.approx.f16x2 %0, %1;" : "=r"(y) : "r"(x));
    return y;
}
__device__ __forceinline__ uint32_t hfma2_u(uint32_t a, uint32_t b, uint32_t c) {
    uint32_t d;
    asm("fma.rn.f16x2 %0, %1, %2, %3;" : "=r"(d) : "r"(a), "r"(b), "r"(c));
    return d;
}
__device__ __forceinline__ float2 h2_to_f2(uint32_t h) {
    float lo, hi;
    asm("{.reg .f16 l, h;\n\t"
        " mov.b32 {l, h}, %2;\n\t"
        " cvt.f32.f16 %0, l;\n\t"
        " cvt.f32.f16 %1, h;}"
        : "=f"(lo), "=f"(hi) : "r"(h));
    return make_float2(lo, hi);
}
__device__ __forceinline__ uint32_t f2_to_h2(float lo, float hi) {
    uint32_t d;
    asm("cvt.rn.f16x2.f32 %0, %2, %1;" : "=r"(d) : "f"(lo), "f"(hi));
    return d;
}

// ---------------- generic fp32 GEMM: out = A[M,K] @ B[K,N] + bias ----------------
template<int KDIM, int NDIM, int MODE>
__global__ void __launch_bounds__(256) sgemm_kernel(
    const float* __restrict__ A, const float* __restrict__ B,
    const float* __restrict__ bias,
    float* __restrict__ out0, float* __restrict__ out1)
{
    constexpr int BM = 128, BN = 64, BK = 16;
    __shared__ float As[BK][BM];
    __shared__ float Bs[BK][BN];

    const int tid  = threadIdx.x;
    const int bx   = blockIdx.x;
    const int by   = blockIdx.y;
    const int tRow = tid >> 4;
    const int tCol = tid & 15;

    float acc[8][4];
#pragma unroll
    for (int i = 0; i < 8; i++)
#pragma unroll
        for (int j = 0; j < 4; j++) acc[i][j] = 0.f;

    const int aRow = tid >> 2;
    const int aC   = (tid & 3) * 4;
    const int bRow = tid >> 4;
    const int bC   = (tid & 15) * 4;

    for (int kt = 0; kt < KDIM; kt += BK) {
#pragma unroll
        for (int l = 0; l < 2; l++) {
            int r = aRow + l * 64;
            float4 v = *reinterpret_cast<const float4*>(
                &A[(size_t)(bx * BM + r) * KDIM + kt + aC]);
            As[aC + 0][r] = v.x; As[aC + 1][r] = v.y;
            As[aC + 2][r] = v.z; As[aC + 3][r] = v.w;
        }
        {
            float4 v = *reinterpret_cast<const float4*>(
                &B[(size_t)(kt + bRow) * NDIM + by * BN + bC]);
            *reinterpret_cast<float4*>(&Bs[bRow][bC]) = v;
        }
        __syncthreads();
#pragma unroll
        for (int k = 0; k < BK; k++) {
            float am[8], bn[4];
#pragma unroll
            for (int i = 0; i < 8; i++) am[i] = As[k][tRow * 8 + i];
#pragma unroll
            for (int j = 0; j < 4; j++) bn[j] = Bs[k][tCol * 4 + j];
#pragma unroll
            for (int i = 0; i < 8; i++)
#pragma unroll
                for (int j = 0; j < 4; j++)
                    acc[i][j] = fmaf(am[i], bn[j], acc[i][j]);
        }
        __syncthreads();
    }

#pragma unroll
    for (int i = 0; i < 8; i++) {
#pragma unroll
        for (int j = 0; j < 4; j++) {
            size_t row = (size_t)bx * BM + tRow * 8 + i;
            int col = by * BN + tCol * 4 + j;
            float v = acc[i][j] + bias[col];
            if (MODE == 0) {
                v = tanhf(v);
                if (col < IDIM) out0[row * IDIM + col] = v;
                else            out1[row * SDIM + (col - IDIM)] = v;
            } else if (MODE == 1) {
                out0[row * SDIM + col] = v;
            } else {
                out0[row * MDIM + col] = v;
            }
        }
    }
}

// ---------------- parameter transform + per-s constant sums ----------------
__global__ void param_prep(
    const float* __restrict__ w,   const float* __restrict__ sigma,
    const float* __restrict__ mu,  const float* __restrict__ erev,
    const float* __restrict__ mask,
    const float* __restrict__ sw_, const float* __restrict__ ssig,
    const float* __restrict__ smu, const float* __restrict__ serev,
    const float* __restrict__ smask)
{
    int s = threadIdx.x;  // 128 threads, 1 block
    float cns = 0.f, cds = 0.f;
    for (int i = 0; i < IDIM; i++) {
        int idx = i * SDIM + s;
        float a  = 0.5f * ssig[idx];
        g_sens_ab[idx] = make_float2(a, -smu[idx] * a);
        float wh = 0.5f * sw_[idx] * smask[idx];
        float we = wh * serev[idx];
        g_sens_wv[idx] = make_float2(we, wh);
        cns += we; cds += wh;
    }
    g_cns[s] = cns; g_cds[s] = cds;

    float cnr = 0.f, cdr = 0.f;
    for (int j = 0; j < SDIM; j++) {
        int idx = j * SDIM + s;
        float wh = 0.5f * w[idx] * mask[idx];
        float we = wh * erev[idx];
        g_rec_wh[idx] = wh; g_rec_we[idx] = we;
        cnr += we; cdr += wh;
    }
    g_cnr[s] = cnr; g_cdr[s] = cdr;

    // packed half2 recurrent (a,b) for j-pairs
    for (int p = 0; p < NPAIR; p++) {
        int j0 = 2 * p, j1 = 2 * p + 1;
        float a0 = 0.5f * sigma[j0 * SDIM + s];
        float a1 = 0.5f * sigma[j1 * SDIM + s];
        float b0 = -mu[j0 * SDIM + s] * a0;
        float b1 = -mu[j1 * SDIM + s] * a1;
        g_rec_ab2[p * SDIM + s] = make_uint2(f2_to_h2(a0, a1), f2_to_h2(b0, b1));
    }
}

// ---------------- softmax over T (axis=1) + sigmoid + multiply by C ----------------
__global__ void __launch_bounds__(512) softmax_m_kernel()
{
    __shared__ float red[512];
    const int b = blockIdx.x, tid = threadIdx.x;
    const int s = tid & 127, tc = tid >> 7;
    const float* g  = g_gate + (size_t)b * TSEQ * SDIM;
    const float* Cb = g_C    + (size_t)b * TSEQ * SDIM;
    float*       mb = g_m    + (size_t)b * TSEQ * SDIM;
    const int t0 = tc * 256;

    float mx = -1e30f;
    for (int t = t0; t < t0 + 256; t++) mx = fmaxf(mx, g[t * SDIM + s]);
    red[tid] = mx;
    __syncthreads();
    mx = fmaxf(fmaxf(red[s], red[128 + s]), fmaxf(red[256 + s], red[384 + s]));
    __syncthreads();

    float sum = 0.f;
    for (int t = t0; t < t0 + 256; t++) sum += __expf(g[t * SDIM + s] - mx);
    red[tid] = sum;
    __syncthreads();
    sum = red[s] + red[128 + s] + red[256 + s] + red[384 + s];
    float inv = __fdividef(1.0f, sum);

    for (int t = t0; t < t0 + 256; t++) {
        float e  = __expf(g[t * SDIM + s] - mx) * inv;
        float sg = fmaf(0.5f, tanh_fast(0.5f * e), 0.5f);  // sigmoid(e)
        mb[t * SDIM + s] = Cb[t * SDIM + s] * sg;
    }
}

// ---------------- sensory precompute ----------------
__global__ void __launch_bounds__(128) sensory_kernel(const float* __restrict__ hidden)
{
    __shared__ float h_sm[16][IDIM];
    const int tid = threadIdx.x;
    const size_t row0 = (size_t)blockIdx.x * 16;

    for (int idx = tid; idx < 16 * IDIM; idx += 128)
        h_sm[idx >> 8][idx & 255] = hidden[row0 * IDIM + idx];
    __syncthreads();

    const int s = tid;
    float an[16], ad[16];
#pragma unroll
    for (int r = 0; r < 16; r++) { an[r] = 0.f; ad[r] = 0.f; }

    for (int i = 0; i < IDIM; i++) {
        float2 ab = g_sens_ab[i * SDIM + s];
        float2 wv = g_sens_wv[i * SDIM + s];
#pragma unroll
        for (int r = 0; r < 16; r++) {
            float th = tanh_fast(fmaf(h_sm[r][i], ab.x, ab.y));
            an[r] = fmaf(wv.x, th, an[r]);
            ad[r] = fmaf(wv.y, th, ad[r]);
        }
    }
    const float cn = g_cns[s], cd = g_cds[s];
#pragma unroll
    for (int r = 0; r < 16; r++) {
        g_wns[(row0 + r) * SDIM + s] = an[r] + cn;
        g_wds[(row0 + r) * SDIM + s] = ad[r] + cd;
    }
}

// ---------------- sequential ODE scan: f16x2 tanh, fp32 state/accum ----------------
// 1 CTA / batch, 512 threads. Writes fused + final_state DIRECTLY into d_out tail.
__global__ void __launch_bounds__(512) scan_kernel(
    const float* __restrict__ ode_state,
    const float* __restrict__ gleak, const float* __restrict__ vleak,
    const float* __restrict__ cm,
    float* __restrict__ fused_out, float* __restrict__ final_out)
{
    __shared__ uint32_t v2_sm[NPAIR];   // packed half2 of v (pairs of j)
    __shared__ float red[1024];

    const int b = blockIdx.x, tid = threadIdx.x;
    const int s = tid & 127, jg = tid >> 7;

    // per-thread fp32 mixing weights for j = jg*32 .. jg*32+31
    float whr[32], wer[32];
#pragma unroll
    for (int k = 0; k < 32; k++) {
        int j = jg * 32 + k;
        whr[k] = g_rec_wh[j * SDIM + s];
        wer[k] = g_rec_we[j * SDIM + s];
    }

    float cmt = 0.f, gl = 0.f, glvl = 0.f, crn = 0.f, crd = 0.f, v = 0.f;
    if (jg == 0) {
        cmt  = 6.0f * cm[s];
        gl   = gleak[s];
        glvl = gl * vleak[s];
        crn  = g_cnr[s];
        crd  = g_cdr[s];
        v    = ode_state[b * SDIM + s];
        reinterpret_cast<__half*>(v2_sm)[s] = __float2half_rn(v);
    }
    __syncthreads();

    const float* wnsb = g_wns + (size_t)b * TSEQ * SDIM;
    const float* wdsb = g_wds + (size_t)b * TSEQ * SDIM;
    const float* mb   = g_m   + (size_t)b * TSEQ * SDIM;
    float*       fb   = fused_out + (size_t)b * TSEQ * SDIM;

    const uint2* __restrict__ ab2 = g_rec_ab2;

    for (int t = 0; t < TSEQ; t++) {
        float wn = 0.f, wd = 0.f, mt = 0.f;
        if (jg == 0) {
            wn = wnsb[t * SDIM + s];
            wd = wdsb[t * SDIM + s];
            mt = mb  [t * SDIM + s];
        }
#pragma unroll 1
        for (int u = 0; u < UNFOLDS; u++) {
            float pn = 0.f, pd = 0.f;
#pragma unroll
            for (int k = 0; k < 16; k++) {
                int p = jg * 16 + k;                       // j pair (2p, 2p+1)
                uint32_t vv = v2_sm[p];                    // broadcast LDS
                uint2    ab = __ldg(&ab2[p * SDIM + s]);   // L1-resident params
                uint32_t th = tanh_h2(hfma2_u(vv, ab.x, ab.y));
                float2   f  = h2_to_f2(th);
                pn = fmaf(wer[2 * k], f.x, fmaf(wer[2 * k + 1], f.y, pn));
                pd = fmaf(whr[2 * k], f.x, fmaf(whr[2 * k + 1], f.y, pd));
            }
            red[tid]       = pn;
            red[512 + tid] = pd;
            __syncthreads();
            if (jg == 0) {
                float num = fmaf(cmt, v, glvl) + wn + crn
                          + red[s] + red[128 + s] + red[256 + s] + red[384 + s];
                float den = cmt + gl + wd + crd
                          + red[512 + s] + red[640 + s] + red[768 + s] + red[896 + s];
                v = __fdividef(num, den + 1e-8f);
                reinterpret_cast<__half*>(v2_sm)[s] = __float2half_rn(v);
            }
            __syncthreads();
        }
        if (jg == 0) fb[t * SDIM + s] = v * mt;
    }
    if (jg == 0) final_out[b * SDIM + s] = v;
}

// ---------------- launch ----------------
extern "C" void kernel_launch(void* const* d_in, const int* in_sizes, int n_in,
                              void* d_out, int out_size)
{
    const float* inputs   = (const float*)d_in[0];
    const float* ode_st   = (const float*)d_in[1];
    const float* W_in     = (const float*)d_in[2];
    const float* b_in     = (const float*)d_in[3];
    const float* W_c      = (const float*)d_in[4];
    const float* b_c      = (const float*)d_in[5];
    const float* W_out    = (const float*)d_in[6];
    const float* b_out    = (const float*)d_in[7];
    const float* gleak    = (const float*)d_in[8];
    const float* vleak    = (const float*)d_in[9];
    const float* cm       = (const float*)d_in[10];
    const float* w        = (const float*)d_in[11];
    const float* sigma    = (const float*)d_in[12];
    const float* mu       = (const float*)d_in[13];
    const float* sens_w   = (const float*)d_in[14];
    const float* sens_sig = (const float*)d_in[15];
    const float* sens_mu  = (const float*)d_in[16];
    const float* erev     = (const float*)d_in[17];
    const float* sens_er  = (const float*)d_in[18];
    const float* mask     = (const float*)d_in[19];
    const float* sens_msk = (const float*)d_in[20];
    (void)in_sizes; (void)n_in; (void)out_size;

    // d_out layout (verified passing): [outputs BT*M][final_state B*S][fused BT*S]
    float* outputs = (float*)d_out;
    float* finalp  = outputs + (size_t)BT * MDIM;
    float* fusedp  = finalp  + (size_t)BATCH * SDIM;

    // Resolve TRUE device addresses of scratch symbols (host-side symbol decay
    // gives the host shadow address, which ATS silently accepts on GB300).
    float *p_hidden = nullptr, *p_gate = nullptr, *p_C = nullptr;
    cudaGetSymbolAddress((void**)&p_hidden, g_hidden);
    cudaGetSymbolAddress((void**)&p_gate,   g_gate);
    cudaGetSymbolAddress((void**)&p_C,      g_C);

    param_prep<<<1, 128>>>(w, sigma, mu, erev, mask,
                           sens_w, sens_sig, sens_mu, sens_er, sens_msk);
    sgemm_kernel<FDIM, IDIM + SDIM, 0><<<dim3(BT / 128, (IDIM + SDIM) / 64), 256>>>(
        inputs, W_in, b_in, p_hidden, p_gate);
    sgemm_kernel<IDIM, SDIM, 1><<<dim3(BT / 128, SDIM / 64), 256>>>(
        p_hidden, W_c, b_c, p_C, nullptr);
    softmax_m_kernel<<<BATCH, 512>>>();
    sensory_kernel<<<BT / 16, 128>>>(p_hidden);
    scan_kernel<<<BATCH, 512>>>(ode_st, gleak, vleak, cm, fusedp, finalp);
    sgemm_kernel<SDIM, MDIM, 2><<<dim3(BT / 128, 1), 256>>>(
        fusedp, W_out, b_out, outputs, nullptr);
}